// round 16
// baseline (speedup 1.0000x reference)
#include <cuda_runtime.h>
#include <cuda_fp16.h>
#include <cstdint>
#include <math.h>

// Problem constants: B=8, T=2048, D=1024, E=8 -> BT=16384
#define D_DIM 1024
#define E_DIM 8
#define BT_MAX 16384

__device__ float g_mix[BT_MAX * E_DIM];
__device__ __half g_xh[BT_MAX * D_DIM];            // 32 MB fp16 copy of x
__device__ __half g_wh[E_DIM * D_DIM * D_DIM];     // 16 MB fp16 copy of Wg

// ===========================================================================
// PTX helpers
// ===========================================================================
__device__ __forceinline__ uint32_t smem_u32(const void* p) {
    uint32_t a;
    asm("{ .reg .u64 t; cvta.to.shared.u64 t, %1; cvt.u32.u64 %0, t; }" : "=r"(a) : "l"(p));
    return a;
}

#define CP_ASYNC16(dst, src) \
    asm volatile("cp.async.cg.shared.global [%0], [%1], 16;" :: "r"(dst), "l"(src) : "memory")

#define CP_ASYNC_ARRIVE_NOINC(mbar) \
    asm volatile("cp.async.mbarrier.arrive.noinc.shared::cta.b64 [%0];" :: "r"(mbar) : "memory")

#define MBARRIER_INIT(addr, cnt) \
    asm volatile("mbarrier.init.shared.b64 [%0], %1;" :: "r"(addr), "r"(cnt) : "memory")

#define MBARRIER_ARRIVE(addr) \
    asm volatile("mbarrier.arrive.shared.b64 _, [%0];" :: "r"(addr) : "memory")

#define MBARRIER_WAIT_PARITY(addr, ph) do {                                      \
    uint32_t _m = (addr); uint32_t _p = (ph); uint32_t _d;                       \
    asm volatile("{\n\t.reg .pred p;\n\t"                                        \
        "mbarrier.try_wait.parity.acquire.cta.shared::cta.b64 p, [%1], %2;\n\t"  \
        "selp.b32 %0, 1, 0, p;\n\t}"                                             \
        : "=r"(_d) : "r"(_m), "r"(_p) : "memory");                               \
    if (!_d) {                                                                   \
        asm volatile("{\n\t.reg .pred P1;\n\t"                                   \
        "W%=:\n\t"                                                               \
        "mbarrier.try_wait.parity.acquire.cta.shared::cta.b64 P1, [%0], %1, 0x989680;\n\t" \
        "@P1 bra.uni DN%=;\n\t"                                                  \
        "bra.uni W%=;\n\t"                                                       \
        "DN%=:\n\t}" :: "r"(_m), "r"(_p) : "memory");                            \
    } } while (0)

__device__ __forceinline__ void ldmatrix_x4(uint32_t* r, uint32_t addr) {
    asm volatile("ldmatrix.sync.aligned.m8n8.x4.shared.b16 {%0,%1,%2,%3}, [%4];"
        : "=r"(r[0]), "=r"(r[1]), "=r"(r[2]), "=r"(r[3]) : "r"(addr));
}

__device__ __forceinline__ void mma16n8k16h(float* d, const uint32_t* a, const uint32_t* b) {
    asm volatile("mma.sync.aligned.m16n8k16.row.col.f32.f16.f16.f32 "
        "{%0,%1,%2,%3}, {%4,%5,%6,%7}, {%8,%9}, {%0,%1,%2,%3};"
        : "+f"(d[0]), "+f"(d[1]), "+f"(d[2]), "+f"(d[3])
        : "r"(a[0]), "r"(a[1]), "r"(a[2]), "r"(a[3]), "r"(b[0]), "r"(b[1]));
}

// ===========================================================================
// Kernel 0: fp32 -> fp16 conversion (W only; x is converted inside routing)
// ===========================================================================
__global__ __launch_bounds__(256) void f2h_kernel(const float* __restrict__ src,
                                                  __half* __restrict__ dst, int n)
{
    int i = (blockIdx.x * 256 + threadIdx.x) * 4;
    if (i < n) {
        float4 v = *(const float4*)(src + i);
        __half2 h0 = __floats2half2_rn(v.x, v.y);
        __half2 h1 = __floats2half2_rn(v.z, v.w);
        uint2 u;
        u.x = *(uint32_t*)&h0;
        u.y = *(uint32_t*)&h1;
        *(uint2*)(dst + i) = u;
    }
}

// ===========================================================================
// Kernel 1: routing (float4 loads) + fused x -> fp16 conversion.
//   One warp per token. Lane owns elements [lane*4 + 128*j .. +3], j=0..7.
// ===========================================================================
__global__ __launch_bounds__(128) void routing_kernel(
    const float* __restrict__ x,
    const float* __restrict__ Wf, const float* __restrict__ bf,
    const float* __restrict__ Wt, const float* __restrict__ bt,
    const float* __restrict__ alpha, int BT)
{
    int warp = blockIdx.x * (blockDim.x >> 5) + (threadIdx.x >> 5);
    int lane = threadIdx.x & 31;
    if (warp >= BT) return;

    const float* xr = x + (size_t)warp * D_DIM;
    float4 xv[8];
#pragma unroll
    for (int j = 0; j < 8; ++j)
        xv[j] = *(const float4*)(xr + lane * 4 + 128 * j);

    // fused fp16 conversion of x
    {
        __half* xhr = g_xh + (size_t)warp * D_DIM;
#pragma unroll
        for (int j = 0; j < 8; ++j) {
            __half2 h0 = __floats2half2_rn(xv[j].x, xv[j].y);
            __half2 h1 = __floats2half2_rn(xv[j].z, xv[j].w);
            uint2 u;
            u.x = *(uint32_t*)&h0;
            u.y = *(uint32_t*)&h1;
            *(uint2*)(xhr + lane * 4 + 128 * j) = u;
        }
    }

    float dots[16];
#pragma unroll
    for (int r = 0; r < 16; ++r) {
        const float* w = (r < 8) ? (Wt + r * D_DIM) : (Wf + (r - 8) * D_DIM);
        float s = 0.0f;
#pragma unroll
        for (int j = 0; j < 8; ++j) {
            float4 wv = *(const float4*)(w + lane * 4 + 128 * j);
            s += xv[j].x * wv.x + xv[j].y * wv.y + xv[j].z * wv.z + xv[j].w * wv.w;
        }
#pragma unroll
        for (int off = 16; off > 0; off >>= 1)
            s += __shfl_xor_sync(0xffffffffu, s, off);
        dots[r] = s;
    }

    float tl[8], fl[8];
#pragma unroll
    for (int e = 0; e < 8; ++e) { tl[e] = dots[e] + bt[e]; fl[e] = dots[8 + e] + bf[e]; }

    float v0 = tl[0]; int i0 = 0;
    float v1 = -INFINITY; int i1 = -1;
#pragma unroll
    for (int e = 1; e < 8; ++e) {
        if (tl[e] > v0) { v1 = v0; i1 = i0; v0 = tl[e]; i0 = e; }
        else if (tl[e] > v1) { v1 = tl[e]; i1 = e; }
    }
    float p1 = expf(v1 - v0);
    float sv0 = 1.0f / (1.0f + p1);
    float sv1 = p1 * sv0;

    float mf = fl[0];
#pragma unroll
    for (int e = 1; e < 8; ++e) mf = fmaxf(mf, fl[e]);
    float ef[8]; float se = 0.0f;
#pragma unroll
    for (int e = 0; e < 8; ++e) { ef[e] = expf(fl[e] - mf); se += ef[e]; }
    float inv_se = 1.0f / se;

    float a = 1.0f / (1.0f + expf(-alpha[0]));
    float one_m_a = 1.0f - a;

#pragma unroll
    for (int e = 0; e < 8; ++e) {
        float tp = (e == i0) ? sv0 : ((e == i1) ? sv1 : 0.0f);
        float m = a * tp + one_m_a * ef[e] * inv_se;
        if (lane == e) g_mix[(size_t)warp * E_DIM + e] = m;
    }
}

// ===========================================================================
// Kernel 2: fp16 mma.sync fused MoE gate, 256 threads, 2 CTAs/SM.
//   CTA tile 128(m) x 128(n); 8 warps (2m x 4n); warp tile 64x32; m16n8k16.
//   BK=64; XOR-swizzled smem; 3 buffers, prefetch distance 2; mbarrier
//   pipeline; per-expert fold via gmem read-modify-write.
// ===========================================================================
#define F_BM 128
#define F_BN 128
#define F_BK 64
#define ST_B 16384u                       // A (or B) stage bytes: 128r * 128B
#define KCH (D_DIM / F_BK)                // 16 k-chunks per expert
#define N_FLAT (E_DIM * KCH)              // 128
#define N_THREADS 256

// dynamic smem layout (bytes): A 3*16384, B 3*16384, barriers
#define SMB_A    0
#define SMB_B    49152
#define SMB_BAR  98304                    // full[3] @ +0, empty[3] @ +24
#define SMEM_BYTES 98368

__global__ __launch_bounds__(N_THREADS, 2) void moe_gate_h(
    const float* __restrict__ bg,
    float* __restrict__ out)
{
    extern __shared__ char smc[];

    const int tid = threadIdx.x;
    const int warp = tid >> 5, lane = tid & 31;
    const int wm = (warp & 1) * 64;       // 2 m-warps
    const int wn = (warp >> 1) * 32;      // 4 n-warps
    const int g = lane >> 2, tg = lane & 3;
    const int m0 = blockIdx.y * F_BM, n0 = blockIdx.x * F_BN;

    const uint32_t sAs = smem_u32(smc + SMB_A);
    const uint32_t sBs = smem_u32(smc + SMB_B);
    const uint32_t sBar = smem_u32(smc + SMB_BAR);
    // full[s] = sBar + s*8 ; empty[s] = sBar + 24 + s*8

    // ---- hoisted ldmatrix addressing (swizzled; byte offsets within a stage)
    const uint32_t rowA = (uint32_t)(wm + (lane & 15));       // +16 per mf
    const uint32_t mA = (rowA & 7u) << 4;                     // invariant under +16
    const uint32_t cHiA = ((uint32_t)(lane >> 4)) << 4;
    const uint32_t aRowBase = rowA * 128u;
    const uint32_t rowB = (uint32_t)(wn + (lane & 7) + (((lane >> 4) & 1) << 3));
    const uint32_t mB = ((uint32_t)(lane & 7)) << 4;
    const uint32_t cLoB = ((uint32_t)((lane >> 3) & 1)) << 4;
    const uint32_t bRowBase = rowB * 128u;

    uint32_t colA[4], colB[4];
#pragma unroll
    for (int kki = 0; kki < 4; ++kki) {
        const uint32_t kk2 = (uint32_t)(kki * 32);
        colA[kki] = (kk2 | cHiA) ^ mA;
        colB[kki] = (kk2 | cLoB) ^ mB;
    }

    // ---- hoisted loader addressing: rows ldR (+32,+64,+96), 16B chunk ldQ
    const int ldR = tid >> 3, ldQ = tid & 7;          // ldR in [0,32)
    const uint32_t ldSwz = (uint32_t)(ldR * 128 + ((ldQ * 16) ^ ((ldR & 7) << 4)));
    const __half* ldA = g_xh + (size_t)(m0 + ldR) * D_DIM + ldQ * 8;
    const __half* ldB = g_wh + (size_t)(n0 + ldR) * D_DIM + ldQ * 8;

    if (tid == 0) {
#pragma unroll
        for (int s = 0; s < 3; ++s) {
            MBARRIER_INIT(sBar + s * 8, N_THREADS);   // full[s]: cp.async arrivals
            MBARRIER_INIT(sBar + 24 + s * 8, 8);      // empty[s]: 1 arrive/warp
        }
    }
    __syncthreads();

#define H_ISSUE(st, a, b) do {                                                       \
    const uint32_t _aD = sAs + (uint32_t)(st) * ST_B + ldSwz;                        \
    const uint32_t _bD = sBs + (uint32_t)(st) * ST_B + ldSwz;                        \
    CP_ASYNC16(_aD,           (a));                                                  \
    CP_ASYNC16(_aD + 4096u,   (a) + 32 * D_DIM);                                     \
    CP_ASYNC16(_aD + 8192u,   (a) + 64 * D_DIM);                                     \
    CP_ASYNC16(_aD + 12288u,  (a) + 96 * D_DIM);                                     \
    CP_ASYNC16(_bD,           (b));                                                  \
    CP_ASYNC16(_bD + 4096u,   (b) + 32 * D_DIM);                                     \
    CP_ASYNC16(_bD + 8192u,   (b) + 64 * D_DIM);                                     \
    CP_ASYNC16(_bD + 12288u,  (b) + 96 * D_DIM);                                     \
    CP_ASYNC_ARRIVE_NOINC(sBar + (uint32_t)(st) * 8u);                               \
} while (0)

#define H_COMPUTE(st) do {                                                           \
    const uint32_t aB = sAs + (uint32_t)(st) * ST_B + aRowBase;                      \
    const uint32_t bB = sBs + (uint32_t)(st) * ST_B + bRowBase;                      \
    _Pragma("unroll")                                                                \
    for (int kki = 0; kki < 4; ++kki) {                                              \
        uint32_t bfr[4][2];                                                          \
        {                                                                            \
            uint32_t r[4];                                                           \
            ldmatrix_x4(r, bB + colB[kki]);                                          \
            bfr[0][0] = r[0]; bfr[0][1] = r[1]; bfr[1][0] = r[2]; bfr[1][1] = r[3];  \
            ldmatrix_x4(r, bB + 2048u + colB[kki]);                                  \
            bfr[2][0] = r[0]; bfr[2][1] = r[1]; bfr[3][0] = r[2]; bfr[3][1] = r[3];  \
        }                                                                            \
        _Pragma("unroll")                                                            \
        for (int mf = 0; mf < 4; ++mf) {                                             \
            uint32_t afr[4];                                                         \
            ldmatrix_x4(afr, aB + (uint32_t)(mf * 2048) + colA[kki]);                \
            _Pragma("unroll")                                                        \
            for (int nf = 0; nf < 4; ++nf)                                           \
                mma16n8k16h(acc[mf][nf], afr, bfr[nf]);                              \
        }                                                                            \
    }                                                                                \
} while (0)

// fold expert e into gmem out (RMW; e==0 overwrites the poisoned buffer)
#define H_FOLD(eVal) do {                                                            \
    const int _e = (eVal);                                                           \
    const float* _bgE = bg + (size_t)_e * D_DIM + n0;                                \
    _Pragma("unroll")                                                                \
    for (int mf = 0; mf < 4; ++mf) {                                                 \
        const int _r0 = m0 + wm + mf * 16 + g;                                       \
        const float mx0 = __ldg(g_mix + (size_t)_r0 * E_DIM + _e);                   \
        const float mx1 = __ldg(g_mix + (size_t)(_r0 + 8) * E_DIM + _e);             \
        _Pragma("unroll")                                                            \
        for (int nf = 0; nf < 4; ++nf) {                                             \
            const int _c = wn + nf * 8 + 2 * tg;                                     \
            const float b0 = __ldg(_bgE + _c);                                       \
            const float b1 = __ldg(_bgE + _c + 1);                                   \
            const float v0 = mx0 / (1.0f + __expf(-(acc[mf][nf][0] + b0)));          \
            const float v1 = mx0 / (1.0f + __expf(-(acc[mf][nf][1] + b1)));          \
            const float v2 = mx1 / (1.0f + __expf(-(acc[mf][nf][2] + b0)));          \
            const float v3 = mx1 / (1.0f + __expf(-(acc[mf][nf][3] + b1)));          \
            float2* _p0 = (float2*)(out + (size_t)_r0 * D_DIM + n0 + _c);            \
            float2* _p1 = (float2*)(out + (size_t)(_r0 + 8) * D_DIM + n0 + _c);      \
            if (_e == 0) {                                                           \
                __stcg(_p0, make_float2(v0, v1));                                    \
                __stcg(_p1, make_float2(v2, v3));                                    \
            } else {                                                                 \
                float2 o0 = __ldcg(_p0), o1 = __ldcg(_p1);                           \
                o0.x += v0; o0.y += v1; o1.x += v2; o1.y += v3;                      \
                __stcg(_p0, o0); __stcg(_p1, o1);                                    \
            }                                                                        \
            acc[mf][nf][0] = 0.0f; acc[mf][nf][1] = 0.0f;                            \
            acc[mf][nf][2] = 0.0f; acc[mf][nf][3] = 0.0f;                            \
        }                                                                            \
    }                                                                                \
} while (0)

    float acc[4][4][4];
#pragma unroll
    for (int a = 0; a < 4; ++a)
#pragma unroll
        for (int b = 0; b < 4; ++b)
#pragma unroll
            for (int c = 0; c < 4; ++c) acc[a][b][c] = 0.0f;

    // prologue: fill stages 0, 1 (buffers 0, 1)
    H_ISSUE(0, ldA, ldB);
    H_ISSUE(1, ldA + 64, ldB + 64);
    const __half* pfA = ldA + 128;   // next fill = stage 2 (k-chunk 2, expert 0)
    const __half* pfB = ldB + 128;
    int pfK = 2;

    // main: 42 blocks of 3 (t = 0..125); fills stages 3j+2, 3j+3, 3j+4 (d=2)
    for (int j = 0; j < 42; ++j) {
        const uint32_t pj  = (uint32_t)(j & 1);
        const uint32_t pjm = (uint32_t)((j - 1) & 1);

        // ---- u = 0: fill stage 3j+2 (buf 2, fill #j), consume t=3j (buf 0)
        if (j >= 1) MBARRIER_WAIT_PARITY(sBar + 24u + 16u, pjm);
        H_ISSUE(2, pfA, pfB);
        pfA += 64; pfB += 64;
        if (++pfK == KCH) { pfK = 0; pfA -= 1024; pfB += (D_DIM * D_DIM - 1024); }
        MBARRIER_WAIT_PARITY(sBar, pj);
        H_COMPUTE(0);
        if (lane == 0) MBARRIER_ARRIVE(sBar + 24u);

        // ---- u = 1: fill stage 3j+3 (buf 0, fill #j+1), consume t=3j+1 (buf 1)
        MBARRIER_WAIT_PARITY(sBar + 24u, pj);
        H_ISSUE(0, pfA, pfB);
        pfA += 64; pfB += 64;
        if (++pfK == KCH) { pfK = 0; pfA -= 1024; pfB += (D_DIM * D_DIM - 1024); }
        MBARRIER_WAIT_PARITY(sBar + 8u, pj);
        H_COMPUTE(1);
        if (lane == 0) MBARRIER_ARRIVE(sBar + 24u + 8u);

        // ---- u = 2: fill stage 3j+4 (buf 1, fill #j+1), consume t=3j+2 (buf 2)
        MBARRIER_WAIT_PARITY(sBar + 24u + 8u, pj);
        H_ISSUE(1, pfA, pfB);
        pfA += 64; pfB += 64;
        if (++pfK == KCH) { pfK = 0; pfA -= 1024; pfB += (D_DIM * D_DIM - 1024); }
        MBARRIER_WAIT_PARITY(sBar + 16u, pj);
        H_COMPUTE(2);
        if (lane == 0) MBARRIER_ARRIVE(sBar + 24u + 16u);

        const int t2 = 3 * j + 2;
        if ((t2 & 15) == 15) H_FOLD(t2 >> 4);        // t = 15,31,...,111 all ≡ 3j+2? no:
        // folds happen at t & 15 == 15; t in {15,31,47,63,79,95,111} within the loop.
        // 15=3*4+3? 15 = 3j+u -> j=5,u=0; handle all three slots:
        // (checked below per-slot instead)
        (void)t2;
    }

    // NOTE: fold points t=15(j5,u0),31(j10,u1),47(j15,u2),63(j21,u0),79(j26,u1),
    // 95(j31,u2),111(j37,u0) are inside the loop above — handled via the checks
    // below (recompute): to keep the loop branch-light we ran folds lazily here
    // is NOT possible (acc must reset). So the loop above must fold in-slot:
    // the (t&15)==15 checks are integrated by re-deriving t per slot:
    //   u0: t=3j   -> fold when (3j&15)==15   (j=5,21,37)
    //   u1: t=3j+1 -> fold when ((3j+1)&15)==15 (j=10,26)
    //   u2: t=3j+2 -> fold when ((3j+2)&15)==15 (j=15,31)
    // These are rare; implemented via the cheap tests inside the loop — see
    // the corrected loop below (this placeholder loop was replaced).

    // tail: t = 126 (buf 0, fill #42 -> parity 0), t = 127 (buf 1, fill #42)
    MBARRIER_WAIT_PARITY(sBar, 0u);
    H_COMPUTE(0);
    MBARRIER_WAIT_PARITY(sBar + 8u, 0u);
    H_COMPUTE(1);
    H_FOLD(7);
}

// The fold-in-slot requirement makes the unrolled loop above subtle; to keep
// correctness airtight the kernel actually used is moe_gate_h2 below, which
// integrates the fold checks per slot. moe_gate_h is unused.

__global__ __launch_bounds__(N_THREADS, 2) void moe_gate_h2(
    const float* __restrict__ bg,
    float* __restrict__ out)
{
    extern __shared__ char smc[];

    const int tid = threadIdx.x;
    const int warp = tid >> 5, lane = tid & 31;
    const int wm = (warp & 1) * 64;
    const int wn = (warp >> 1) * 32;
    const int g = lane >> 2, tg = lane & 3;
    const int m0 = blockIdx.y * F_BM, n0 = blockIdx.x * F_BN;

    const uint32_t sAs = smem_u32(smc + SMB_A);
    const uint32_t sBs = smem_u32(smc + SMB_B);
    const uint32_t sBar = smem_u32(smc + SMB_BAR);

    const uint32_t rowA = (uint32_t)(wm + (lane & 15));
    const uint32_t mA = (rowA & 7u) << 4;
    const uint32_t cHiA = ((uint32_t)(lane >> 4)) << 4;
    const uint32_t aRowBase = rowA * 128u;
    const uint32_t rowB = (uint32_t)(wn + (lane & 7) + (((lane >> 4) & 1) << 3));
    const uint32_t mB = ((uint32_t)(lane & 7)) << 4;
    const uint32_t cLoB = ((uint32_t)((lane >> 3) & 1)) << 4;
    const uint32_t bRowBase = rowB * 128u;

    uint32_t colA[4], colB[4];
#pragma unroll
    for (int kki = 0; kki < 4; ++kki) {
        const uint32_t kk2 = (uint32_t)(kki * 32);
        colA[kki] = (kk2 | cHiA) ^ mA;
        colB[kki] = (kk2 | cLoB) ^ mB;
    }

    const int ldR = tid >> 3, ldQ = tid & 7;
    const uint32_t ldSwz = (uint32_t)(ldR * 128 + ((ldQ * 16) ^ ((ldR & 7) << 4)));
    const __half* ldA = g_xh + (size_t)(m0 + ldR) * D_DIM + ldQ * 8;
    const __half* ldB = g_wh + (size_t)(n0 + ldR) * D_DIM + ldQ * 8;

    if (tid == 0) {
#pragma unroll
        for (int s = 0; s < 3; ++s) {
            MBARRIER_INIT(sBar + s * 8, N_THREADS);
            MBARRIER_INIT(sBar + 24 + s * 8, 8);
        }
    }
    __syncthreads();

    float acc[4][4][4];
#pragma unroll
    for (int a = 0; a < 4; ++a)
#pragma unroll
        for (int b = 0; b < 4; ++b)
#pragma unroll
            for (int c = 0; c < 4; ++c) acc[a][b][c] = 0.0f;

    H_ISSUE(0, ldA, ldB);
    H_ISSUE(1, ldA + 64, ldB + 64);
    const __half* pfA = ldA + 128;
    const __half* pfB = ldB + 128;
    int pfK = 2;

#define H_ADV() do {                                                                 \
    pfA += 64; pfB += 64;                                                            \
    if (++pfK == KCH) { pfK = 0; pfA -= 1024; pfB += (D_DIM * D_DIM - 1024); }       \
} while (0)

    for (int j = 0; j < 42; ++j) {
        const uint32_t pj  = (uint32_t)(j & 1);
        const uint32_t pjm = (uint32_t)((j - 1) & 1);
        const int t0 = 3 * j;

        // u=0: fill 3j+2 (buf2 #j), consume 3j (buf0)
        if (j >= 1) MBARRIER_WAIT_PARITY(sBar + 40u, pjm);
        H_ISSUE(2, pfA, pfB); H_ADV();
        MBARRIER_WAIT_PARITY(sBar, pj);
        H_COMPUTE(0);
        if (lane == 0) MBARRIER_ARRIVE(sBar + 24u);
        if ((t0 & 15) == 15) H_FOLD(t0 >> 4);

        // u=1: fill 3j+3 (buf0 #j+1), consume 3j+1 (buf1)
        MBARRIER_WAIT_PARITY(sBar + 24u, pj);
        H_ISSUE(0, pfA, pfB); H_ADV();
        MBARRIER_WAIT_PARITY(sBar + 8u, pj);
        H_COMPUTE(1);
        if (lane == 0) MBARRIER_ARRIVE(sBar + 32u);
        if (((t0 + 1) & 15) == 15) H_FOLD((t0 + 1) >> 4);

        // u=2: fill 3j+4 (buf1 #j+1), consume 3j+2 (buf2)
        MBARRIER_WAIT_PARITY(sBar + 32u, pj);
        H_ISSUE(1, pfA, pfB); H_ADV();
        MBARRIER_WAIT_PARITY(sBar + 16u, pj);
        H_COMPUTE(2);
        if (lane == 0) MBARRIER_ARRIVE(sBar + 40u);
        if (((t0 + 2) & 15) == 15) H_FOLD((t0 + 2) >> 4);
    }

    // tail: t=126 (buf0, fill #42 -> parity 0), t=127 (buf1, fill #42 -> parity 0)
    MBARRIER_WAIT_PARITY(sBar, 0u);
    H_COMPUTE(0);
    MBARRIER_WAIT_PARITY(sBar + 8u, 0u);
    H_COMPUTE(1);
    H_FOLD(7);
}

// ===========================================================================
// Inputs: x, Wg, bg, Wf, bf, Wt, bt, alpha, num
// ===========================================================================
extern "C" void kernel_launch(void* const* d_in, const int* in_sizes, int n_in,
                              void* d_out, int out_size)
{
    const float* x     = (const float*)d_in[0];
    const float* Wg    = (const float*)d_in[1];
    const float* bg    = (const float*)d_in[2];
    const float* Wf    = (const float*)d_in[3];
    const float* bf    = (const float*)d_in[4];
    const float* Wt    = (const float*)d_in[5];
    const float* bt    = (const float*)d_in[6];
    const float* alpha = (const float*)d_in[7];
    float* out = (float*)d_out;

    const int BT = in_sizes[0] / D_DIM;    // 16384
    const int n_w = E_DIM * D_DIM * D_DIM; // 8388608

    __half* wh_ptr = nullptr;
    cudaGetSymbolAddress((void**)&wh_ptr, g_wh);

    cudaFuncSetAttribute(moe_gate_h2,
                         cudaFuncAttributeMaxDynamicSharedMemorySize, SMEM_BYTES);

    f2h_kernel<<<n_w / 1024, 256>>>(Wg, wh_ptr, n_w);

    routing_kernel<<<(BT + 3) / 4, 128>>>(x, Wf, bf, Wt, bt, alpha, BT);

    dim3 grid(D_DIM / F_BN, BT / F_BM);   // (8, 128) = 1024 CTAs
    moe_gate_h2<<<grid, N_THREADS, SMEM_BYTES>>>(bg, out);
}

// round 17
// speedup vs baseline: 1.0485x; 1.0485x over previous
#include <cuda_runtime.h>
#include <cuda_fp16.h>
#include <cstdint>
#include <math.h>

// Problem constants: B=8, T=2048, D=1024, E=8 -> BT=16384
#define D_DIM 1024
#define E_DIM 8
#define BT_MAX 16384

__device__ float g_mix[BT_MAX * E_DIM];
__device__ __half g_xh[BT_MAX * D_DIM];            // 32 MB fp16 copy of x
__device__ __half g_wh[E_DIM * D_DIM * D_DIM];     // 16 MB fp16 copy of Wg

// ===========================================================================
// PTX helpers
// ===========================================================================
__device__ __forceinline__ uint32_t smem_u32(const void* p) {
    uint32_t a;
    asm("{ .reg .u64 t; cvta.to.shared.u64 t, %1; cvt.u32.u64 %0, t; }" : "=r"(a) : "l"(p));
    return a;
}

#define CP_ASYNC16(dst, src) \
    asm volatile("cp.async.cg.shared.global [%0], [%1], 16;" :: "r"(dst), "l"(src) : "memory")

#define CP_ASYNC_ARRIVE_NOINC(mbar) \
    asm volatile("cp.async.mbarrier.arrive.noinc.shared::cta.b64 [%0];" :: "r"(mbar) : "memory")

#define MBARRIER_INIT(addr, cnt) \
    asm volatile("mbarrier.init.shared.b64 [%0], %1;" :: "r"(addr), "r"(cnt) : "memory")

#define MBARRIER_ARRIVE(addr) \
    asm volatile("mbarrier.arrive.shared.b64 _, [%0];" :: "r"(addr) : "memory")

#define MBARRIER_WAIT_PARITY(addr, ph) do {                                      \
    uint32_t _m = (addr); uint32_t _p = (ph); uint32_t _d;                       \
    asm volatile("{\n\t.reg .pred p;\n\t"                                        \
        "mbarrier.try_wait.parity.acquire.cta.shared::cta.b64 p, [%1], %2;\n\t"  \
        "selp.b32 %0, 1, 0, p;\n\t}"                                             \
        : "=r"(_d) : "r"(_m), "r"(_p) : "memory");                               \
    if (!_d) {                                                                   \
        asm volatile("{\n\t.reg .pred P1;\n\t"                                   \
        "W%=:\n\t"                                                               \
        "mbarrier.try_wait.parity.acquire.cta.shared::cta.b64 P1, [%0], %1, 0x989680;\n\t" \
        "@P1 bra.uni DN%=;\n\t"                                                  \
        "bra.uni W%=;\n\t"                                                       \
        "DN%=:\n\t}" :: "r"(_m), "r"(_p) : "memory");                            \
    } } while (0)

__device__ __forceinline__ void ldmatrix_x4(uint32_t* r, uint32_t addr) {
    asm volatile("ldmatrix.sync.aligned.m8n8.x4.shared.b16 {%0,%1,%2,%3}, [%4];"
        : "=r"(r[0]), "=r"(r[1]), "=r"(r[2]), "=r"(r[3]) : "r"(addr));
}

__device__ __forceinline__ void mma16n8k16h(float* d, const uint32_t* a, const uint32_t* b) {
    asm volatile("mma.sync.aligned.m16n8k16.row.col.f32.f16.f16.f32 "
        "{%0,%1,%2,%3}, {%4,%5,%6,%7}, {%8,%9}, {%0,%1,%2,%3};"
        : "+f"(d[0]), "+f"(d[1]), "+f"(d[2]), "+f"(d[3])
        : "r"(a[0]), "r"(a[1]), "r"(a[2]), "r"(a[3]), "r"(b[0]), "r"(b[1]));
}

// ===========================================================================
// Kernel 0: fp32 -> fp16 conversion (W only; x converted inside routing)
// ===========================================================================
__global__ __launch_bounds__(256) void f2h_kernel(const float* __restrict__ src,
                                                  __half* __restrict__ dst, int n)
{
    int i = (blockIdx.x * 256 + threadIdx.x) * 4;
    if (i < n) {
        float4 v = *(const float4*)(src + i);
        __half2 h0 = __floats2half2_rn(v.x, v.y);
        __half2 h1 = __floats2half2_rn(v.z, v.w);
        uint2 u;
        u.x = *(uint32_t*)&h0;
        u.y = *(uint32_t*)&h1;
        *(uint2*)(dst + i) = u;
    }
}

// ===========================================================================
// Kernel 1: routing (float4 loads) + fused x -> fp16 conversion (from R16,
// measured rel_err-identical).
// ===========================================================================
__global__ __launch_bounds__(128) void routing_kernel(
    const float* __restrict__ x,
    const float* __restrict__ Wf, const float* __restrict__ bf,
    const float* __restrict__ Wt, const float* __restrict__ bt,
    const float* __restrict__ alpha, int BT)
{
    int warp = blockIdx.x * (blockDim.x >> 5) + (threadIdx.x >> 5);
    int lane = threadIdx.x & 31;
    if (warp >= BT) return;

    const float* xr = x + (size_t)warp * D_DIM;
    float4 xv[8];
#pragma unroll
    for (int j = 0; j < 8; ++j)
        xv[j] = *(const float4*)(xr + lane * 4 + 128 * j);

    // fused fp16 conversion of x
    {
        __half* xhr = g_xh + (size_t)warp * D_DIM;
#pragma unroll
        for (int j = 0; j < 8; ++j) {
            __half2 h0 = __floats2half2_rn(xv[j].x, xv[j].y);
            __half2 h1 = __floats2half2_rn(xv[j].z, xv[j].w);
            uint2 u;
            u.x = *(uint32_t*)&h0;
            u.y = *(uint32_t*)&h1;
            *(uint2*)(xhr + lane * 4 + 128 * j) = u;
        }
    }

    float dots[16];
#pragma unroll
    for (int r = 0; r < 16; ++r) {
        const float* w = (r < 8) ? (Wt + r * D_DIM) : (Wf + (r - 8) * D_DIM);
        float s = 0.0f;
#pragma unroll
        for (int j = 0; j < 8; ++j) {
            float4 wv = *(const float4*)(w + lane * 4 + 128 * j);
            s += xv[j].x * wv.x + xv[j].y * wv.y + xv[j].z * wv.z + xv[j].w * wv.w;
        }
#pragma unroll
        for (int off = 16; off > 0; off >>= 1)
            s += __shfl_xor_sync(0xffffffffu, s, off);
        dots[r] = s;
    }

    float tl[8], fl[8];
#pragma unroll
    for (int e = 0; e < 8; ++e) { tl[e] = dots[e] + bt[e]; fl[e] = dots[8 + e] + bf[e]; }

    float v0 = tl[0]; int i0 = 0;
    float v1 = -INFINITY; int i1 = -1;
#pragma unroll
    for (int e = 1; e < 8; ++e) {
        if (tl[e] > v0) { v1 = v0; i1 = i0; v0 = tl[e]; i0 = e; }
        else if (tl[e] > v1) { v1 = tl[e]; i1 = e; }
    }
    float p1 = expf(v1 - v0);
    float sv0 = 1.0f / (1.0f + p1);
    float sv1 = p1 * sv0;

    float mf = fl[0];
#pragma unroll
    for (int e = 1; e < 8; ++e) mf = fmaxf(mf, fl[e]);
    float ef[8]; float se = 0.0f;
#pragma unroll
    for (int e = 0; e < 8; ++e) { ef[e] = expf(fl[e] - mf); se += ef[e]; }
    float inv_se = 1.0f / se;

    float a = 1.0f / (1.0f + expf(-alpha[0]));
    float one_m_a = 1.0f - a;

#pragma unroll
    for (int e = 0; e < 8; ++e) {
        float tp = (e == i0) ? sv0 : ((e == i1) ? sv1 : 0.0f);
        float m = a * tp + one_m_a * ef[e] * inv_se;
        if (lane == e) g_mix[(size_t)warp * E_DIM + e] = m;
    }
}

// ===========================================================================
// Kernel 2: EXACT R14 GEMM (measured 672us, at crossbar floor).
//   fp16 mma.sync fused MoE gate, 256 threads, 2 CTAs/SM.
//   CTA tile 128(m) x 64(n); warp grid 4m x 2n; warp tile 32x32; m16n8k16.
//   BK=64; XOR-swizzled smem; 4 stage buffers; mbarrier producer/consumer
//   pipeline (no block barrier in mainloop); incremental prefetch pointers.
// ===========================================================================
#define F_BM 128
#define F_BN 64
#define F_BK 64
#define AST_B 16384u               // A stage bytes: 128 rows * 128 B
#define BST_B 8192u                // B stage bytes:  64 rows * 128 B
#define N_STAGES 4
#define KCH (D_DIM / F_BK)                // 16 k-chunks per expert
#define N_FLAT (E_DIM * KCH)              // 128
#define N_THREADS 256

// dynamic smem layout (bytes)
#define SMB_A    0                         // 4 * 16384 = 65536
#define SMB_B    65536                     // 4 *  8192 = 32768
#define SMB_MIX  98304                     // 4096 B
#define SMB_BGS  102400                    // 2048 B
#define SMB_BAR  104448                    // 8 mbarriers * 8 B = 64 B
#define SMEM_BYTES 104512

__global__ __launch_bounds__(N_THREADS, 2) void moe_gate_h(
    const float* __restrict__ bg,
    float* __restrict__ out)
{
    extern __shared__ char smc[];
    float* mixs = (float*)(smc + SMB_MIX);
    float* bgs  = (float*)(smc + SMB_BGS);

    const int tid = threadIdx.x;
    const int warp = tid >> 5, lane = tid & 31;
    const int wm = (warp & 3) * 32;       // 4 m-warps
    const int wn = (warp >> 2) * 32;      // 2 n-warps
    const int g = lane >> 2, tg = lane & 3;
    const int m0 = blockIdx.y * F_BM, n0 = blockIdx.x * F_BN;

    const uint32_t sAs = smem_u32(smc + SMB_A);
    const uint32_t sBs = smem_u32(smc + SMB_B);
    const uint32_t sBar = smem_u32(smc + SMB_BAR);
    // full[s] = sBar + s*8 ; empty[s] = sBar + 32 + s*8

    // ---- hoisted ldmatrix addressing (swizzled; byte offsets within a stage)
    const uint32_t rowA = (uint32_t)(wm + (lane & 15));
    const uint32_t mA = (rowA & 7u) << 4;
    const uint32_t cHiA = ((uint32_t)(lane >> 4)) << 4;
    const uint32_t aRowBase = rowA * 128u;
    const uint32_t rowB = (uint32_t)(wn + (lane & 7) + (((lane >> 4) & 1) << 3));
    const uint32_t mB = ((uint32_t)(lane & 7)) << 4;
    const uint32_t cLoB = ((uint32_t)((lane >> 3) & 1)) << 4;
    const uint32_t bRowBase = rowB * 128u;

    uint32_t colA[4], colB[4];
#pragma unroll
    for (int kki = 0; kki < 4; ++kki) {
        const uint32_t kk2 = (uint32_t)(kki * 32);
        colA[kki] = (kk2 | cHiA) ^ mA;
        colB[kki] = (kk2 | cLoB) ^ mB;
    }

    // ---- hoisted loader addressing: rows ldR (+32,+64,+96), 16B chunk ldQ
    const int ldR = tid >> 3, ldQ = tid & 7;          // ldR in [0,32)
    const uint32_t ldSwz = (uint32_t)(ldR * 128 + ((ldQ * 16) ^ ((ldR & 7) << 4)));
    const __half* ldA = g_xh + (size_t)(m0 + ldR) * D_DIM + ldQ * 8;
    const __half* ldB = g_wh + (size_t)(n0 + ldR) * D_DIM + ldQ * 8;

    // init barriers + preload mix/bg tiles
    if (tid == 0) {
#pragma unroll
        for (int s = 0; s < 4; ++s) {
            MBARRIER_INIT(sBar + s * 8, N_THREADS);   // full[s]
            MBARRIER_INIT(sBar + 32 + s * 8, 8);      // empty[s], 1 arrive/warp
        }
    }
    ((float4*)mixs)[tid] = ((const float4*)(g_mix + (size_t)m0 * E_DIM))[tid];
    if (tid < 128) {
        const int e = tid >> 4, c = (tid & 15) * 4;
        *(float4*)(bgs + e * F_BN + c) = *(const float4*)(bg + (size_t)e * D_DIM + n0 + c);
    }
    __syncthreads();

#define H_ISSUE(st, a, b) do {                                                       \
    const uint32_t _aD = sAs + (uint32_t)(st) * AST_B + ldSwz;                       \
    const uint32_t _bD = sBs + (uint32_t)(st) * BST_B + ldSwz;                       \
    CP_ASYNC16(_aD,              (a));                                               \
    CP_ASYNC16(_aD + 32u * 128u, (a) + 32 * D_DIM);                                  \
    CP_ASYNC16(_aD + 64u * 128u, (a) + 64 * D_DIM);                                  \
    CP_ASYNC16(_aD + 96u * 128u, (a) + 96 * D_DIM);                                  \
    CP_ASYNC16(_bD,              (b));                                               \
    CP_ASYNC16(_bD + 32u * 128u, (b) + 32 * D_DIM);                                  \
    CP_ASYNC_ARRIVE_NOINC(sBar + (uint32_t)(st) * 8u);                               \
} while (0)

#define H_COMPUTE(st) do {                                                           \
    const uint32_t aB = sAs + (uint32_t)(st) * AST_B + aRowBase;                     \
    const uint32_t bB = sBs + (uint32_t)(st) * BST_B + bRowBase;                     \
    _Pragma("unroll")                                                                \
    for (int kki = 0; kki < 4; ++kki) {                                              \
        uint32_t afr[2][4], bfr[4][2];                                               \
        ldmatrix_x4(afr[0], aB + colA[kki]);                                         \
        ldmatrix_x4(afr[1], aB + 2048u + colA[kki]);                                 \
        {                                                                            \
            uint32_t r[4];                                                           \
            ldmatrix_x4(r, bB + colB[kki]);                                          \
            bfr[0][0] = r[0]; bfr[0][1] = r[1]; bfr[1][0] = r[2]; bfr[1][1] = r[3];  \
            ldmatrix_x4(r, bB + 2048u + colB[kki]);                                  \
            bfr[2][0] = r[0]; bfr[2][1] = r[1]; bfr[3][0] = r[2]; bfr[3][1] = r[3];  \
        }                                                                            \
        _Pragma("unroll")                                                            \
        for (int mf = 0; mf < 2; ++mf)                                               \
            _Pragma("unroll")                                                        \
            for (int nf = 0; nf < 4; ++nf)                                           \
                mma16n8k16h(acc[mf][nf], afr[mf], bfr[nf]);                          \
    }                                                                                \
} while (0)

#define H_FOLD(eVal) do {                                                            \
    const int _e = (eVal);                                                           \
    _Pragma("unroll")                                                                \
    for (int mf = 0; mf < 2; ++mf) {                                                 \
        const int r = wm + mf * 16 + g;                                              \
        const float mx0 = mixs[r * E_DIM + _e];                                      \
        const float mx1 = mixs[(r + 8) * E_DIM + _e];                                \
        _Pragma("unroll")                                                            \
        for (int nf = 0; nf < 4; ++nf) {                                             \
            const int c = wn + nf * 8 + 2 * tg;                                      \
            const float b0 = bgs[_e * F_BN + c];                                     \
            const float b1 = bgs[_e * F_BN + c + 1];                                 \
            accOut[mf][nf][0] += mx0 / (1.0f + __expf(-(acc[mf][nf][0] + b0)));      \
            accOut[mf][nf][1] += mx0 / (1.0f + __expf(-(acc[mf][nf][1] + b1)));      \
            accOut[mf][nf][2] += mx1 / (1.0f + __expf(-(acc[mf][nf][2] + b0)));      \
            accOut[mf][nf][3] += mx1 / (1.0f + __expf(-(acc[mf][nf][3] + b1)));      \
            acc[mf][nf][0] = 0.0f; acc[mf][nf][1] = 0.0f;                            \
            acc[mf][nf][2] = 0.0f; acc[mf][nf][3] = 0.0f;                            \
        }                                                                            \
    }                                                                                \
} while (0)

    // prologue: fill stages 0,1 (buffers 0,1; first use, no empty wait)
    H_ISSUE(0, ldA, ldB);
    H_ISSUE(1, ldA + 64, ldB + 64);

    // incremental prefetch pointers (next fill = stage 2: k-chunk 2, expert 0)
    const __half* pfA = ldA + 128;
    const __half* pfB = ldB + 128;
    int pfK = 2;

    float accOut[2][4][4];
#pragma unroll
    for (int a = 0; a < 2; ++a)
#pragma unroll
        for (int b = 0; b < 4; ++b)
#pragma unroll
            for (int c = 0; c < 4; ++c) accOut[a][b][c] = 0.0f;

    float acc[2][4][4];
#pragma unroll
    for (int a = 0; a < 2; ++a)
#pragma unroll
        for (int b = 0; b < 4; ++b)
#pragma unroll
            for (int c = 0; c < 4; ++c) acc[a][b][c] = 0.0f;

    // mainloop: consume stage t, fill stage t+2 (prefetch distance 2)
#pragma unroll 4
    for (int t = 0; t < N_FLAT; ++t) {
        const int u = t + 2;
        if (u < N_FLAT) {
            if (u >= N_STAGES) {
                // buffer (u&3) free once all warps consumed stage u-4
                MBARRIER_WAIT_PARITY(sBar + 32u + (uint32_t)(u & 3) * 8u,
                                     (uint32_t)(((u >> 2) - 1) & 1));
            }
            H_ISSUE(u & 3, pfA, pfB);
            pfA += 64; pfB += 64;
            if (++pfK == KCH) { pfK = 0; pfA -= 1024; pfB += (D_DIM * D_DIM - 1024); }
        }

        // wait stage t data (full barrier flipped (t>>2)+1 times)
        MBARRIER_WAIT_PARITY(sBar + (uint32_t)(t & 3) * 8u, (uint32_t)((t >> 2) & 1));
        H_COMPUTE(t & 3);
        if (lane == 0) MBARRIER_ARRIVE(sBar + 32u + (uint32_t)(t & 3) * 8u);

        if ((t & (KCH - 1)) == KCH - 1)
            H_FOLD(t >> 4);
    }

    // write 128x64 tile (each warp: 32 rows x 32 cols)
#pragma unroll
    for (int mf = 0; mf < 2; ++mf) {
        const int r0 = m0 + wm + mf * 16 + g;
#pragma unroll
        for (int nf = 0; nf < 4; ++nf) {
            const int c = n0 + wn + nf * 8 + 2 * tg;
            *(float2*)(out + (size_t)r0 * D_DIM + c) =
                make_float2(accOut[mf][nf][0], accOut[mf][nf][1]);
            *(float2*)(out + (size_t)(r0 + 8) * D_DIM + c) =
                make_float2(accOut[mf][nf][2], accOut[mf][nf][3]);
        }
    }
}

// ===========================================================================
// Inputs: x, Wg, bg, Wf, bf, Wt, bt, alpha, num
// ===========================================================================
extern "C" void kernel_launch(void* const* d_in, const int* in_sizes, int n_in,
                              void* d_out, int out_size)
{
    const float* x     = (const float*)d_in[0];
    const float* Wg    = (const float*)d_in[1];
    const float* bg    = (const float*)d_in[2];
    const float* Wf    = (const float*)d_in[3];
    const float* bf    = (const float*)d_in[4];
    const float* Wt    = (const float*)d_in[5];
    const float* bt    = (const float*)d_in[6];
    const float* alpha = (const float*)d_in[7];
    float* out = (float*)d_out;

    const int BT = in_sizes[0] / D_DIM;    // 16384
    const int n_w = E_DIM * D_DIM * D_DIM; // 8388608

    __half* wh_ptr = nullptr;
    cudaGetSymbolAddress((void**)&wh_ptr, g_wh);

    cudaFuncSetAttribute(moe_gate_h,
                         cudaFuncAttributeMaxDynamicSharedMemorySize, SMEM_BYTES);

    f2h_kernel<<<n_w / 1024, 256>>>(Wg, wh_ptr, n_w);

    routing_kernel<<<(BT + 3) / 4, 128>>>(x, Wf, bf, Wt, bt, alpha, BT);

    dim3 grid(D_DIM / F_BN, BT / F_BM);   // (16, 128) = 2048 CTAs
    moe_gate_h<<<grid, N_THREADS, SMEM_BYTES>>>(bg, out);
}